// round 1
// baseline (speedup 1.0000x reference)
#include <cuda_runtime.h>
#include <math.h>

// Problem constants
#define Bb 4
#define Tt 2048
#define Dd 2048
#define DH 1024
#define KK 16
#define NH 16
#define HD 128
#define BT (Bb*Tt)          // 8192 rows
#define KPAD 1032           // dh+1 padded to multiple of 8

// ---------------- scratch (device globals; no allocation) ----------------
__device__ float g_S0[(size_t)BT * Dd];     // ln outputs / ctx
__device__ float g_S1[(size_t)BT * Dd];     // sheaf pre / Q
__device__ float g_repr[64 * Dd];           // gist_repr
__device__ float g_Kh[64 * Dd];
__device__ float g_Vv[64 * Dd];
__device__ float g_packin[64 * KPAD];
__device__ float g_Wpad[Dd * KPAD];
__device__ float g_shc[4 * DH];
__device__ float g_shs[4 * DH];
__device__ float g_gc[Bb * DH];
__device__ float g_gs[Bb * DH];

// ---------------- block reduction (sum of two values) ----------------
__device__ __forceinline__ void block_reduce2(float& a, float& b, float* sh)
{
    __syncthreads();   // protect shared reuse across consecutive calls
#pragma unroll
    for (int o = 16; o > 0; o >>= 1) {
        a += __shfl_xor_sync(0xffffffffu, a, o);
        b += __shfl_xor_sync(0xffffffffu, b, o);
    }
    int warp = threadIdx.x >> 5, lane = threadIdx.x & 31;
    if (lane == 0) { sh[warp] = a; sh[8 + warp] = b; }
    __syncthreads();
    if (threadIdx.x < 32) {
        float aa = (lane < 8) ? sh[lane] : 0.f;
        float bb = (lane < 8) ? sh[8 + lane] : 0.f;
#pragma unroll
        for (int o = 4; o > 0; o >>= 1) {
            aa += __shfl_xor_sync(0xffffffffu, aa, o);
            bb += __shfl_xor_sync(0xffffffffu, bb, o);
        }
        if (lane == 0) { sh[16] = aa; sh[17] = bb; }
    }
    __syncthreads();
    a = sh[16]; b = sh[17];
}

// ---------------- LayerNorm: y = LN(x)*w + b, one block per row ----------------
__global__ void __launch_bounds__(256) ln_kernel(const float* __restrict__ x,
                                                 float* __restrict__ y,
                                                 const float* __restrict__ w,
                                                 const float* __restrict__ b)
{
    __shared__ float sh[32];
    size_t row = blockIdx.x;
    const float* xr = x + row * Dd;
    float v[8]; float s = 0.f, s2 = 0.f;
#pragma unroll
    for (int i = 0; i < 8; i++) {
        v[i] = xr[threadIdx.x + (i << 8)];
        s += v[i]; s2 += v[i] * v[i];
    }
    block_reduce2(s, s2, sh);
    float mu = s * (1.f / Dd);
    float inv = rsqrtf(s2 * (1.f / Dd) - mu * mu + 1e-5f);
    float* yr = y + row * Dd;
#pragma unroll
    for (int i = 0; i < 8; i++) {
        int idx = threadIdx.x + (i << 8);
        yr[idx] = (v[i] - mu) * inv * w[idx] + b[idx];
    }
}

// ---------------- cos/sin of sheaf thetas ----------------
__global__ void sheaf_cs_kernel(const float* __restrict__ th,
                                float* __restrict__ c, float* __restrict__ s)
{
    int i = blockIdx.x * blockDim.x + threadIdx.x;
    if (i < 4 * DH) { float t = th[i]; c[i] = cosf(t); s[i] = sinf(t); }
}

// ---------------- sheaf: pre = xln - |alpha| * lap ----------------
// lap = 4*xln[t] - sum_idx rot_inv(xln[t+delta], c_idx, s_idx), delta = idx-3
__global__ void __launch_bounds__(256) sheaf_pre_kernel(const float* __restrict__ xln,
                                                        float* __restrict__ pre,
                                                        const float* __restrict__ cs,
                                                        const float* __restrict__ sn,
                                                        const float* __restrict__ alpha_p)
{
    int row = blockIdx.x;
    int b = row / Tt, t = row % Tt;
    float a = fabsf(alpha_p[0]);
    const float* xr = xln + (size_t)row * Dd;
    float* pr = pre + (size_t)row * Dd;
#pragma unroll
    for (int ii = 0; ii < 4; ii++) {
        int j = threadIdx.x + (ii << 8);
        float xre = xr[j], xim = xr[j + DH];
        float lr = 4.f * xre, li = 4.f * xim;
#pragma unroll
        for (int idx = 0; idx < 4; idx++) {
            int tn = t + (idx - 3);
            float yr = 0.f, yi = 0.f;
            if (tn >= 0) {
                const float* y = xln + ((size_t)b * Tt + tn) * Dd;
                yr = y[j]; yi = y[j + DH];
            }
            float c = cs[idx * DH + j], ss = sn[idx * DH + j];
            lr -= yr * c + yi * ss;          // rot_inv real part
            li -= yi * c - yr * ss;          // rot_inv imag part
        }
        pr[j]      = xre - a * lr;
        pr[j + DH] = xim - a * li;
    }
}

// ---------------- gist angle cos/sin per (batch, dh) ----------------
__global__ void gist_cs_kernel(const float* __restrict__ gt,   // [B,K,DH]
                               const float* __restrict__ gm,   // [B,K]
                               const float* __restrict__ gw,   // [B,K]
                               const float* __restrict__ strength,
                               float* __restrict__ c, float* __restrict__ s)
{
    int i = blockIdx.x * blockDim.x + threadIdx.x;
    if (i >= Bb * DH) return;
    int b = i / DH, j = i % DH;
    float sig = 1.f / (1.f + expf(-strength[0]));
    float wsum = 0.f, th = 0.f;
#pragma unroll
    for (int k = 0; k < KK; k++) {
        float w = gw[b * KK + k] * gm[b * KK + k];
        wsum += w;
        th += w * gt[(size_t)(b * KK + k) * DH + j];
    }
    th = th / (wsum + 1e-8f) * sig;
    c[i] = cosf(th); s[i] = sinf(th);
}

// ---------------- fused: xn=LN(x); rot=rotate(xn); x += LN(rot) - xn (in place) ----------------
__global__ void __launch_bounds__(256) gist_fused_kernel(float* __restrict__ x,
    const float* __restrict__ lnw, const float* __restrict__ lnb,
    const float* __restrict__ grw, const float* __restrict__ grb,
    const float* __restrict__ gc, const float* __restrict__ gs)
{
    __shared__ float sh[32];
    size_t row = blockIdx.x;
    int b = blockIdx.x / Tt;
    float* xr = x + row * Dd;
    float v[8]; float s = 0.f, s2 = 0.f;
#pragma unroll
    for (int i = 0; i < 8; i++) {
        v[i] = xr[threadIdx.x + (i << 8)];
        s += v[i]; s2 += v[i] * v[i];
    }
    block_reduce2(s, s2, sh);
    float mu = s * (1.f / Dd);
    float inv = rsqrtf(s2 * (1.f / Dd) - mu * mu + 1e-5f);
    float xn[8];
#pragma unroll
    for (int i = 0; i < 8; i++) {
        int idx = threadIdx.x + (i << 8);
        xn[i] = (v[i] - mu) * inv * lnw[idx] + lnb[idx];
    }
    // rotation: element idx pairs with idx+DH; with stride-256 mapping those are i and i+4
    float rot[8]; float rs = 0.f, rs2 = 0.f;
#pragma unroll
    for (int i = 0; i < 4; i++) {
        int j = threadIdx.x + (i << 8);
        float c = gc[b * DH + j], sn = gs[b * DH + j];
        float r = xn[i], im = xn[i + 4];
        rot[i]     = r * c - im * sn;
        rot[i + 4] = r * sn + im * c;
    }
#pragma unroll
    for (int i = 0; i < 8; i++) { rs += rot[i]; rs2 += rot[i] * rot[i]; }
    block_reduce2(rs, rs2, sh);
    float mu2 = rs * (1.f / Dd);
    float inv2 = rsqrtf(rs2 * (1.f / Dd) - mu2 * mu2 + 1e-5f);
#pragma unroll
    for (int i = 0; i < 8; i++) {
        int idx = threadIdx.x + (i << 8);
        xr[idx] = v[i] + ((rot[i] - mu2) * inv2 * grw[idx] + grb[idx]) - xn[i];
    }
}

// ---------------- pack concat([gist_theta, gist_mag]) into [64, KPAD] ----------------
__global__ void pack_gist_in(const float* __restrict__ gt, const float* __restrict__ gm,
                             float* __restrict__ out)
{
    int i = blockIdx.x * blockDim.x + threadIdx.x;
    if (i >= 64 * KPAD) return;
    int r = i / KPAD, f = i % KPAD;
    float v = 0.f;
    if (f < DH) v = gt[(size_t)r * DH + f];
    else if (f == DH) v = gm[r];
    out[i] = v;
}

__global__ void pad_W_kernel(const float* __restrict__ W, float* __restrict__ out)
{
    int i = blockIdx.x * blockDim.x + threadIdx.x;
    if (i >= Dd * KPAD) return;
    int o = i / KPAD, f = i % KPAD;
    out[i] = (f < DH + 1) ? W[(size_t)o * (DH + 1) + f] : 0.f;
}

// ---------------- SGEMM: C[m,n] = sum_k A[m,k]*W[n,k] (+add1)(+add2)(+bias[n]) ----------------
// 128x128 tile, BK=8, 256 threads, 8x8 per thread, double-buffered smem.
// Requires Kd % 8 == 0 and N % 128 == 0; M arbitrary.
__global__ void __launch_bounds__(256) sgemm_nt(const float* __restrict__ A,
                                                const float* __restrict__ W,
                                                float* __restrict__ C,
                                                const float* __restrict__ add1,
                                                const float* __restrict__ add2,
                                                const float* __restrict__ bias,
                                                int M, int N, int Kd)
{
    __shared__ float As[2][8][128];
    __shared__ float Bs[2][8][128];
    const int tid = threadIdx.x;
    const int bm = blockIdx.y * 128;
    const int bn = blockIdx.x * 128;
    const int lrow = tid >> 1;
    const int lcol = (tid & 1) << 2;
    const int tx = tid & 15;
    const int ty = tid >> 4;
    const int tm0 = ty * 8, tn0 = tx * 8;

    const float* Aptr = A + (size_t)(bm + lrow) * Kd + lcol;
    const float* Wptr = W + (size_t)(bn + lrow) * Kd + lcol;
    const bool a_ok = (bm + lrow) < M;

    float acc[8][8];
#pragma unroll
    for (int i = 0; i < 8; i++)
#pragma unroll
        for (int j = 0; j < 8; j++) acc[i][j] = 0.f;

    float4 pa = a_ok ? *(const float4*)Aptr : make_float4(0.f, 0.f, 0.f, 0.f);
    float4 pb = *(const float4*)Wptr;
    As[0][lcol + 0][lrow] = pa.x; As[0][lcol + 1][lrow] = pa.y;
    As[0][lcol + 2][lrow] = pa.z; As[0][lcol + 3][lrow] = pa.w;
    Bs[0][lcol + 0][lrow] = pb.x; Bs[0][lcol + 1][lrow] = pb.y;
    Bs[0][lcol + 2][lrow] = pb.z; Bs[0][lcol + 3][lrow] = pb.w;
    __syncthreads();

    const int ntiles = Kd >> 3;
    for (int kt = 0; kt < ntiles; kt++) {
        int buf = kt & 1;
        if (kt + 1 < ntiles) {
            pa = a_ok ? *(const float4*)(Aptr + (size_t)(kt + 1) * 8)
                      : make_float4(0.f, 0.f, 0.f, 0.f);
            pb = *(const float4*)(Wptr + (size_t)(kt + 1) * 8);
        }
#pragma unroll
        for (int k = 0; k < 8; k++) {
            float4 a0 = *(const float4*)&As[buf][k][tm0];
            float4 a1 = *(const float4*)&As[buf][k][tm0 + 4];
            float4 b0 = *(const float4*)&Bs[buf][k][tn0];
            float4 b1 = *(const float4*)&Bs[buf][k][tn0 + 4];
            float af[8] = {a0.x, a0.y, a0.z, a0.w, a1.x, a1.y, a1.z, a1.w};
            float bf[8] = {b0.x, b0.y, b0.z, b0.w, b1.x, b1.y, b1.z, b1.w};
#pragma unroll
            for (int i = 0; i < 8; i++)
#pragma unroll
                for (int j = 0; j < 8; j++)
                    acc[i][j] += af[i] * bf[j];
        }
        if (kt + 1 < ntiles) {
            int nb = buf ^ 1;
            As[nb][lcol + 0][lrow] = pa.x; As[nb][lcol + 1][lrow] = pa.y;
            As[nb][lcol + 2][lrow] = pa.z; As[nb][lcol + 3][lrow] = pa.w;
            Bs[nb][lcol + 0][lrow] = pb.x; Bs[nb][lcol + 1][lrow] = pb.y;
            Bs[nb][lcol + 2][lrow] = pb.z; Bs[nb][lcol + 3][lrow] = pb.w;
            __syncthreads();
        }
    }

#pragma unroll
    for (int i = 0; i < 8; i++) {
        int gm = bm + tm0 + i;
        if (gm < M) {
            size_t rowoff = (size_t)gm * N;
#pragma unroll
            for (int j = 0; j < 8; j += 4) {
                int gn = bn + tn0 + j;
                float4 v = make_float4(acc[i][j], acc[i][j + 1], acc[i][j + 2], acc[i][j + 3]);
                if (add1) {
                    float4 t = *(const float4*)(add1 + rowoff + gn);
                    v.x += t.x; v.y += t.y; v.z += t.z; v.w += t.w;
                }
                if (add2) {
                    float4 t = *(const float4*)(add2 + rowoff + gn);
                    v.x += t.x; v.y += t.y; v.z += t.z; v.w += t.w;
                }
                if (bias) {
                    float4 t = *(const float4*)(bias + gn);
                    v.x += t.x; v.y += t.y; v.z += t.z; v.w += t.w;
                }
                *(float4*)(C + rowoff + gn) = v;
            }
        }
    }
}

// ---------------- tiny cross-attention: 16 keys per (b,h), warp per (t,h) ----------------
__global__ void __launch_bounds__(256) attn_kernel(const float* __restrict__ Q,
                                                   const float* __restrict__ Kh,
                                                   const float* __restrict__ Vv,
                                                   float* __restrict__ ctx)
{
    __shared__ float ks[KK][HD];
    __shared__ float vs[KK][HD];
    int bh = blockIdx.y;
    int b = bh >> 4, h = bh & 15;
    for (int i = threadIdx.x; i < KK * HD; i += 256) {
        int k = i >> 7, dd = i & 127;
        size_t off = ((size_t)(b * KK + k)) * Dd + h * HD + dd;
        ks[k][dd] = Kh[off];
        vs[k][dd] = Vv[off];
    }
    __syncthreads();
    int warp = threadIdx.x >> 5, lane = threadIdx.x & 31;
    int t = blockIdx.x * 8 + warp;
    size_t qoff = ((size_t)(b * Tt + t)) * Dd + h * HD + lane * 4;
    float4 q = *(const float4*)(Q + qoff);
    float sc[KK];
#pragma unroll
    for (int k = 0; k < KK; k++) {
        float4 kv = *(const float4*)&ks[k][lane * 4];
        float d = q.x * kv.x + q.y * kv.y + q.z * kv.z + q.w * kv.w;
#pragma unroll
        for (int o = 16; o > 0; o >>= 1) d += __shfl_xor_sync(0xffffffffu, d, o);
        sc[k] = d * 0.088388347648318447f;   // 1/sqrt(128)
    }
    float m = sc[0];
#pragma unroll
    for (int k = 1; k < KK; k++) m = fmaxf(m, sc[k]);
    float ssum = 0.f;
#pragma unroll
    for (int k = 0; k < KK; k++) { sc[k] = expf(sc[k] - m); ssum += sc[k]; }
    float rinv = 1.f / ssum;
    float4 o = make_float4(0.f, 0.f, 0.f, 0.f);
#pragma unroll
    for (int k = 0; k < KK; k++) {
        float p = sc[k] * rinv;
        float4 vv = *(const float4*)&vs[k][lane * 4];
        o.x += p * vv.x; o.y += p * vv.y; o.z += p * vv.z; o.w += p * vv.w;
    }
    *(float4*)(ctx + qoff) = o;
}

// ---------------- orchestration ----------------
extern "C" void kernel_launch(void* const* d_in, const int* in_sizes, int n_in,
                              void* d_out, int out_size)
{
    const float* x            = (const float*)d_in[0];
    const float* gist_theta   = (const float*)d_in[1];
    const float* gist_mag     = (const float*)d_in[2];
    const float* gist_weights = (const float*)d_in[3];
    const float* ln_sheaf_w   = (const float*)d_in[4];
    const float* ln_sheaf_b   = (const float*)d_in[5];
    const float* sheaf_thetas = (const float*)d_in[6];
    const float* alpha        = (const float*)d_in[7];
    const float* corr_W       = (const float*)d_in[8];
    const float* ln_gist_w    = (const float*)d_in[9];
    const float* ln_gist_b    = (const float*)d_in[10];
    const float* gist_strength= (const float*)d_in[11];
    const float* gr_ln_w      = (const float*)d_in[12];
    const float* gr_ln_b      = (const float*)d_in[13];
    const float* ln_gca_w     = (const float*)d_in[14];
    const float* ln_gca_b     = (const float*)d_in[15];
    const float* Wq           = (const float*)d_in[16];
    const float* Wk           = (const float*)d_in[17];
    const float* Wv           = (const float*)d_in[18];
    const float* Wo           = (const float*)d_in[19];
    const float* gist_up_W    = (const float*)d_in[20];
    const float* gist_up_b    = (const float*)d_in[21];
    float* out = (float*)d_out;

    float *S0, *S1, *repr, *Khb, *Vb, *packin, *Wpad, *shc, *shs, *gc, *gs;
    cudaGetSymbolAddress((void**)&S0, g_S0);
    cudaGetSymbolAddress((void**)&S1, g_S1);
    cudaGetSymbolAddress((void**)&repr, g_repr);
    cudaGetSymbolAddress((void**)&Khb, g_Kh);
    cudaGetSymbolAddress((void**)&Vb, g_Vv);
    cudaGetSymbolAddress((void**)&packin, g_packin);
    cudaGetSymbolAddress((void**)&Wpad, g_Wpad);
    cudaGetSymbolAddress((void**)&shc, g_shc);
    cudaGetSymbolAddress((void**)&shs, g_shs);
    cudaGetSymbolAddress((void**)&gc, g_gc);
    cudaGetSymbolAddress((void**)&gs, g_gs);

    dim3 gemm_big(Dd / 128, BT / 128);   // (16, 64)
    dim3 gemm_small(Dd / 128, 1);        // M = 64

    // ---- stage 1: sheaf ----
    ln_kernel<<<BT, 256>>>(x, S0, ln_sheaf_w, ln_sheaf_b);
    sheaf_cs_kernel<<<(4 * DH + 255) / 256, 256>>>(sheaf_thetas, shc, shs);
    sheaf_pre_kernel<<<BT, 256>>>(S0, S1, shc, shs, alpha);
    // out = x + pre + pre @ corr_W^T
    sgemm_nt<<<gemm_big, 256>>>(S1, corr_W, out, x, S1, nullptr, BT, Dd, Dd);

    // ---- stage 2: gist rotation (fused LN -> rotate -> LN -> residual, in place) ----
    gist_cs_kernel<<<(Bb * DH + 255) / 256, 256>>>(gist_theta, gist_mag, gist_weights,
                                                   gist_strength, gc, gs);
    gist_fused_kernel<<<BT, 256>>>(out, ln_gist_w, ln_gist_b, gr_ln_w, gr_ln_b, gc, gs);

    // ---- stage 3: gist cross-attention ----
    pack_gist_in<<<(64 * KPAD + 255) / 256, 256>>>(gist_theta, gist_mag, packin);
    pad_W_kernel<<<(Dd * KPAD + 255) / 256, 256>>>(gist_up_W, Wpad);
    // gist_repr = packin @ Wpad^T + bias
    sgemm_nt<<<gemm_small, 256>>>(packin, Wpad, repr, nullptr, nullptr, gist_up_b,
                                  64, Dd, KPAD);
    sgemm_nt<<<gemm_small, 256>>>(repr, Wk, Khb, nullptr, nullptr, nullptr, 64, Dd, Dd);
    sgemm_nt<<<gemm_small, 256>>>(repr, Wv, Vb, nullptr, nullptr, nullptr, 64, Dd, Dd);
    ln_kernel<<<BT, 256>>>(out, S0, ln_gca_w, ln_gca_b);
    sgemm_nt<<<gemm_big, 256>>>(S0, Wq, S1, nullptr, nullptr, nullptr, BT, Dd, Dd); // Q
    attn_kernel<<<dim3(Tt / 8, Bb * NH), 256>>>(S1, Khb, Vb, S0);                   // ctx
    // out += ctx @ Wo^T
    sgemm_nt<<<gemm_big, 256>>>(S0, Wo, out, out, nullptr, nullptr, BT, Dd, Dd);
}